// round 10
// baseline (speedup 1.0000x reference)
#include <cuda_runtime.h>

// out[i, j] = filt[i] * x[i, j].  Nominal: x [8192, 4096] fp32, filt [8192] fp32.
// Persistent grid-stride kernel: exactly one wave (148 SMs x 8 CTAs), each CTA
// loops over 1024-float4 row-tiles. Per iteration: 4 independent float4 loads
// front-batched (MLP=4), one broadcast filt scalar, streaming cache hints.

#define PERSISTENT_BLOCKS (148 * 8)   // one full wave on GB300 (152 SMs, use 148 floor)

__global__ __launch_bounds__(256) void diag_scale_persist(
    const float4* __restrict__ x,
    const float* __restrict__ filt,
    float4* __restrict__ out,
    int n_tiles,                 // total 1024-float4 tiles
    int tiles_per_row_shift)     // log2(row_f4 / 1024)
{
    int tid = threadIdx.x;
    for (int tile = blockIdx.x; tile < n_tiles; tile += gridDim.x) {
        int row = tile >> tiles_per_row_shift;
        float f = __ldg(&filt[row]);           // L2-resident broadcast

        int base = (tile << 10) + tid;

        float4 v0 = __ldcs(&x[base]);
        float4 v1 = __ldcs(&x[base + 256]);
        float4 v2 = __ldcs(&x[base + 512]);
        float4 v3 = __ldcs(&x[base + 768]);

        v0.x *= f; v0.y *= f; v0.z *= f; v0.w *= f;
        v1.x *= f; v1.y *= f; v1.z *= f; v1.w *= f;
        v2.x *= f; v2.y *= f; v2.z *= f; v2.w *= f;
        v3.x *= f; v3.y *= f; v3.z *= f; v3.w *= f;

        __stcs(&out[base],       v0);
        __stcs(&out[base + 256], v1);
        __stcs(&out[base + 512], v2);
        __stcs(&out[base + 768], v3);
    }
}

// Fallback for shapes that don't tile to 1024 float4 per row chunk.
__global__ __launch_bounds__(256) void diag_scale_scalar_kernel(
    const float* __restrict__ x,
    const float* __restrict__ filt,
    float* __restrict__ out,
    int total, int m)
{
    int idx = blockIdx.x * blockDim.x + threadIdx.x;
    if (idx >= total) return;
    out[idx] = x[idx] * __ldg(&filt[idx / m]);
}

extern "C" void kernel_launch(void* const* d_in, const int* in_sizes, int n_in,
                              void* d_out, int out_size)
{
    const float* x    = (const float*)d_in[0];
    const float* filt = (const float*)d_in[1];
    float* out        = (float*)d_out;

    int total  = in_sizes[0];        // n * m
    int n_filt = in_sizes[1];        // n
    int m      = total / n_filt;     // 4096 nominally

    int row_f4 = m >> 2;             // float4 per row (1024 nominal)
    bool fast = (m % 4 == 0) && (row_f4 >= 1024) && ((row_f4 & (row_f4 - 1)) == 0);

    if (fast) {
        int tiles_per_row = row_f4 >> 10;           // power of two
        int shift = 0;
        while ((1 << shift) < tiles_per_row) shift++;
        int n_tiles = n_filt * tiles_per_row;       // 8192 nominal
        int blocks = n_tiles < PERSISTENT_BLOCKS ? n_tiles : PERSISTENT_BLOCKS;
        diag_scale_persist<<<blocks, 256>>>(
            (const float4*)x, filt, (float4*)out, n_tiles, shift);
    } else {
        int threads = 256;
        int blocks = (total + threads - 1) / threads;
        diag_scale_scalar_kernel<<<blocks, threads>>>(x, filt, out, total, m);
    }
}

// round 11
// speedup vs baseline: 1.0830x; 1.0830x over previous
#include <cuda_runtime.h>

// out[i, j] = filt[i] * x[i, j].  Nominal: x [8192, 4096] fp32, filt [8192] fp32.
// Flat launch, one CTA = one 1024-float4 tile (== one row at m=4096).
// 128 threads x 8 front-batched independent float4 loads (MLP_p1=8 per thread),
// one broadcast filt scalar per block, streaming cache hints (touch-once data).

__global__ __launch_bounds__(128) void diag_scale_row8(
    const float4* __restrict__ x,
    const float* __restrict__ filt,
    float4* __restrict__ out,
    int tiles_per_row_shift)     // log2(row_f4 / 1024)
{
    int tile = blockIdx.x;
    int row  = tile >> tiles_per_row_shift;
    float f  = __ldg(&filt[row]);            // L2-resident broadcast, one per block

    int base = (tile << 10) + threadIdx.x;   // tile * 1024 + tid

    // Front-batch all 8 independent loads (evict-first).
    float4 v0 = __ldcs(&x[base]);
    float4 v1 = __ldcs(&x[base + 128]);
    float4 v2 = __ldcs(&x[base + 256]);
    float4 v3 = __ldcs(&x[base + 384]);
    float4 v4 = __ldcs(&x[base + 512]);
    float4 v5 = __ldcs(&x[base + 640]);
    float4 v6 = __ldcs(&x[base + 768]);
    float4 v7 = __ldcs(&x[base + 896]);

    v0.x *= f; v0.y *= f; v0.z *= f; v0.w *= f;
    v1.x *= f; v1.y *= f; v1.z *= f; v1.w *= f;
    v2.x *= f; v2.y *= f; v2.z *= f; v2.w *= f;
    v3.x *= f; v3.y *= f; v3.z *= f; v3.w *= f;
    v4.x *= f; v4.y *= f; v4.z *= f; v4.w *= f;
    v5.x *= f; v5.y *= f; v5.z *= f; v5.w *= f;
    v6.x *= f; v6.y *= f; v6.z *= f; v6.w *= f;
    v7.x *= f; v7.y *= f; v7.z *= f; v7.w *= f;

    __stcs(&out[base],       v0);
    __stcs(&out[base + 128], v1);
    __stcs(&out[base + 256], v2);
    __stcs(&out[base + 384], v3);
    __stcs(&out[base + 512], v4);
    __stcs(&out[base + 640], v5);
    __stcs(&out[base + 768], v6);
    __stcs(&out[base + 896], v7);
}

// Fallback for shapes that don't tile to 1024 float4 per row chunk.
__global__ __launch_bounds__(256) void diag_scale_scalar_kernel(
    const float* __restrict__ x,
    const float* __restrict__ filt,
    float* __restrict__ out,
    int total, int m)
{
    int idx = blockIdx.x * blockDim.x + threadIdx.x;
    if (idx >= total) return;
    out[idx] = x[idx] * __ldg(&filt[idx / m]);
}

extern "C" void kernel_launch(void* const* d_in, const int* in_sizes, int n_in,
                              void* d_out, int out_size)
{
    const float* x    = (const float*)d_in[0];
    const float* filt = (const float*)d_in[1];
    float* out        = (float*)d_out;

    int total  = in_sizes[0];        // n * m
    int n_filt = in_sizes[1];        // n
    int m      = total / n_filt;     // 4096 nominally

    int row_f4 = m >> 2;             // float4 per row (1024 nominal)
    bool fast = (m % 4 == 0) && (row_f4 >= 1024) && ((row_f4 & (row_f4 - 1)) == 0);

    if (fast) {
        int tiles_per_row = row_f4 >> 10;           // power of two
        int shift = 0;
        while ((1 << shift) < tiles_per_row) shift++;
        int blocks = n_filt * tiles_per_row;        // 8192 nominal
        diag_scale_row8<<<blocks, 128>>>(
            (const float4*)x, filt, (float4*)out, shift);
    } else {
        int threads = 256;
        int blocks = (total + threads - 1) / threads;
        diag_scale_scalar_kernel<<<blocks, threads>>>(x, filt, out, total, m);
    }
}